// round 14
// baseline (speedup 1.0000x reference)
#include <cuda_runtime.h>
#include <cuda_bf16.h>
#include <cstdint>

#define BATCH   8
#define VN      201
#define PAIRS   20301
#define MROWS   162408
#define TILESM  1269
#define KSEL    100
#define LSLOPE  0.01f
#define CNT     323208.0
#define NCTA    148
#define PSTRIDE 160

// smem: header 8KB | A 2 x 32KB (double-buffered hi16+lo16) | B NC*16KB hi + NC*16KB lo
#define OFFA 8192
#define OFFB (OFFA + 65536)

// ---------------- device scratch ----------------
__device__ float g_bufA[MROWS * 256];
__device__ float g_bufB[MROWS * 256];
__device__ int2  g_vw[PAIRS];
__device__ float g_wpair[PAIRS];
__device__ float g_psum[256 * PSTRIDE];
__device__ float g_psq [256 * PSTRIDE];
__device__ float g_sArr[1024];
__device__ float g_tArr[1024];
__device__ float g_logits[BATCH * VN * VN];
__device__ __nv_bfloat16 g_whi[180224];
__device__ __nv_bfloat16 g_wlo[180224];

// ---------------- PTX helpers ----------------
__device__ __forceinline__ uint32_t smem_u32(const void* p) {
    uint32_t a;
    asm("{ .reg .u64 t; cvta.to.shared.u64 t, %1; cvt.u32.u64 %0, t; }" : "=r"(a) : "l"(p));
    return a;
}
#define STS128(r0, r1, r2, r3, a) \
    asm volatile("st.shared.v4.b32 [%0], {%1, %2, %3, %4};" \
                 :: "r"(a), "r"(r0), "r"(r1), "r"(r2), "r"(r3) : "memory")
#define LDSM4(R, a) \
    asm volatile("ldmatrix.sync.aligned.m8n8.x4.shared.b16 {%0,%1,%2,%3}, [%4];" \
                 : "=r"((R)[0]), "=r"((R)[1]), "=r"((R)[2]), "=r"((R)[3]) : "r"(a))
#define MMA16816(c, A, b0, b1) \
    asm volatile("mma.sync.aligned.m16n8k16.row.col.f32.bf16.bf16.f32 " \
                 "{%0,%1,%2,%3}, {%4,%5,%6,%7}, {%8,%9}, {%0,%1,%2,%3};" \
                 : "+f"((c)[0]), "+f"((c)[1]), "+f"((c)[2]), "+f"((c)[3]) \
                 : "r"((A)[0]), "r"((A)[1]), "r"((A)[2]), "r"((A)[3]), "r"(b0), "r"(b1))

// ---------------- init: pair LUT + weight split (fused) ----------------
__global__ void init_all(const float* __restrict__ w0, const float* __restrict__ w1,
                         const float* __restrict__ w2, const float* __restrict__ w3) {
    int t = blockIdx.x * blockDim.x + threadIdx.x;
    int st = gridDim.x * blockDim.x;
    if (blockIdx.x == 0) {
        for (int v = threadIdx.x; v < VN; v += blockDim.x) {
            int base = v * VN - (v * (v - 1)) / 2;
            for (int w = v; w < VN; w++) {
                int p = base + (w - v);
                g_vw[p] = make_int2(v, w);
                g_wpair[p] = (v == w) ? 1.0f : 2.0f;
            }
        }
    }
    for (int i = t; i < 65536; i += st) {
        float v = w0[i]; __nv_bfloat16 h = __float2bfloat16(v);
        g_whi[i] = h; g_wlo[i] = __float2bfloat16(v - __bfloat162float(h));
    }
    for (int i = t; i < 65536; i += st) {
        float v = w1[i]; __nv_bfloat16 h = __float2bfloat16(v);
        g_whi[65536 + i] = h; g_wlo[65536 + i] = __float2bfloat16(v - __bfloat162float(h));
    }
    for (int i = t; i < 32768; i += st) {
        float v = w2[i]; __nv_bfloat16 h = __float2bfloat16(v);
        g_whi[131072 + i] = h; g_wlo[131072 + i] = __float2bfloat16(v - __bfloat162float(h));
    }
    for (int i = t; i < 16384; i += st) {
        float v = w3[i]; __nv_bfloat16 h = __float2bfloat16(v);
        g_whi[163840 + i] = h; g_wlo[163840 + i] = __float2bfloat16(v - __bfloat162float(h));
    }
}

// ---------------- persistent mma.sync bf16-split GEMM: 512 threads, double-buffered A ----------------
// MODE 0: A = |x_v - x_w| on the fly.  MODE 1: A = LeakyReLU(affine(prev)).
// SRC 0: Ain=g_bufA, C=g_bufB.  SRC 1: Ain=g_bufB, C=g_bufA.
template<int K, int MODE, int SRC>
__global__ __launch_bounds__(512, 1)
void gemm_mma(int ldc, int wOff, const float* __restrict__ x,
              const float* __restrict__ bias, int affOff)
{
    constexpr int NC = K / 64;
    const float* Ain  = (SRC == 0) ? g_bufA : g_bufB;
    float*       Cout = (SRC == 0) ? g_bufB : g_bufA;

    extern __shared__ char sm[];
    uint32_t sb = smem_u32(sm);
    const int tid  = threadIdx.x;
    const int lane = tid & 31;
    const int w    = tid >> 5;          // 0..15
    const int wm   = w & 3;             // 4 m-slabs of 32 rows
    const int wn   = w >> 2;            // 4 n-slabs of 32 cols
    const int colStart = blockIdx.y * 128;

    float* biasS  = (float*)(sm + 0);
    float* sumAcc = (float*)(sm + 512);
    float* sqAcc  = (float*)(sm + 1024);
    float* sS     = (float*)(sm + 1536);
    float* tS     = (float*)(sm + 2560);
    float* wSsum  = (float*)(sm + 3584);   // 16 warps x 32
    float* wSsq   = (float*)(sm + 5632);   // 16 warps x 32

    if (tid < 128) { biasS[tid] = bias[colStart + tid]; sumAcc[tid] = 0.f; sqAcc[tid] = 0.f; }
    if (MODE == 1) {
        for (int i = tid; i < K; i += 512) { sS[i] = g_sArr[affOff + i]; tS[i] = g_tArr[affOff + i]; }
    }

    // ---- B (weight hi/lo) resident in smem, SW128 swizzled [n][64k] rows ----
    for (int i = tid; i < NC * 128; i += 512) {
        int c = i >> 7, n = i & 127;
        const uint4* srcH = (const uint4*)(g_whi + (size_t)wOff + (size_t)(colStart + n) * K + c * 64);
        const uint4* srcL = (const uint4*)(g_wlo + (size_t)wOff + (size_t)(colStart + n) * K + c * 64);
        uint32_t baseH = sb + OFFB + c * 16384;
        uint32_t baseL = sb + OFFB + NC * 16384 + c * 16384;
#pragma unroll
        for (int u = 0; u < 8; u++) {
            uint4 vH = srcH[u]; uint4 vL = srcL[u];
            uint32_t o = n * 128 + u * 16; o ^= (o >> 3) & 0x70;
            STS128(vH.x, vH.y, vH.z, vH.w, baseH + o);
            STS128(vL.x, vL.y, vL.z, vL.w, baseL + o);
        }
    }
    __syncthreads();   // B ready

    const int prow = tid >> 2;          // 0..127 (A row)
    const int pq   = tid & 3;           // 16-elem column quarter

    for (int mt = blockIdx.x; mt < TILESM; mt += NCTA) {
        int gr = mt * 128 + prow;
        bool ok = gr < MROWS;
        int vv = 0, ww = 0, bb = 0;
        if (MODE == 0 && ok) {
            bb = gr / PAIRS; int p = gr - bb * PAIRS;
            int2 vw2 = g_vw[p]; vv = vw2.x; ww = vw2.y;
        }

        float facc[2][4][4];
#pragma unroll
        for (int i = 0; i < 2; i++)
#pragma unroll
            for (int j = 0; j < 4; j++)
#pragma unroll
                for (int q = 0; q < 4; q++) facc[i][j][q] = 0.f;

        float fa[16];
        // load chunk 0
        {
            int kb = pq * 16;
            if (ok) {
                if (MODE == 0) {
                    const float4* pv = (const float4*)(x + ((size_t)(bb * VN + vv)) * 256 + kb);
                    const float4* pw = (const float4*)(x + ((size_t)(bb * VN + ww)) * 256 + kb);
#pragma unroll
                    for (int i = 0; i < 4; i++) {
                        float4 fv = pv[i], fw = pw[i];
                        fa[4*i+0] = fabsf(fv.x - fw.x); fa[4*i+1] = fabsf(fv.y - fw.y);
                        fa[4*i+2] = fabsf(fv.z - fw.z); fa[4*i+3] = fabsf(fv.w - fw.w);
                    }
                } else {
                    const float4* pa = (const float4*)(Ain + (size_t)gr * K + kb);
#pragma unroll
                    for (int i = 0; i < 4; i++) {
                        float4 f = pa[i];
                        fa[4*i+0] = f.x; fa[4*i+1] = f.y; fa[4*i+2] = f.z; fa[4*i+3] = f.w;
                    }
                }
            } else {
#pragma unroll
                for (int i = 0; i < 16; i++) fa[i] = 0.f;
            }
        }

        for (int c = 0; c < NC; c++) {
            int kb = c * 64 + pq * 16;
            // convert fa -> hi/lo bf16x2 (affine+act for MODE 1)
            uint32_t hp[8], lp[8];
#pragma unroll
            for (int i = 0; i < 8; i++) {
                float f0 = fa[2*i], f1 = fa[2*i+1];
                if (MODE == 1) {
                    f0 = fmaf(f0, sS[kb + 2*i],     tS[kb + 2*i]);
                    f1 = fmaf(f1, sS[kb + 2*i + 1], tS[kb + 2*i + 1]);
                    f0 = f0 >= 0.f ? f0 : LSLOPE * f0;
                    f1 = f1 >= 0.f ? f1 : LSLOPE * f1;
                }
                uint32_t h;
                asm("cvt.rn.bf16x2.f32 %0, %1, %2;" : "=r"(h) : "f"(f1), "f"(f0));
                __nv_bfloat162 hh = *reinterpret_cast<__nv_bfloat162*>(&h);
                float r0 = f0 - __bfloat162float(hh.x);
                float r1 = f1 - __bfloat162float(hh.y);
                uint32_t l;
                asm("cvt.rn.bf16x2.f32 %0, %1, %2;" : "=r"(l) : "f"(r1), "f"(r0));
                hp[i] = h; lp[i] = l;
            }

            // store into double-buffered A slab (no pre-barrier needed: other buffer
            // was last read at mma(c-2), provably before sync(c-1))
            const uint32_t aH = sb + OFFA + (c & 1) * 32768;
            const uint32_t aL = aH + 16384;
#pragma unroll
            for (int u = 0; u < 2; u++) {
                uint32_t o = prow * 128 + pq * 32 + u * 16; o ^= (o >> 3) & 0x70;
                STS128(hp[4*u], hp[4*u+1], hp[4*u+2], hp[4*u+3], aH + o);
                STS128(lp[4*u], lp[4*u+1], lp[4*u+2], lp[4*u+3], aL + o);
            }
            __syncthreads();   // single barrier per chunk: A(c) visible

            // prefetch next chunk's globals into registers (hidden under mma)
            if (c + 1 < NC) {
                const int kb2 = (c + 1) * 64 + pq * 16;
                if (ok) {
                    if (MODE == 0) {
                        const float4* pv = (const float4*)(x + ((size_t)(bb * VN + vv)) * 256 + kb2);
                        const float4* pw = (const float4*)(x + ((size_t)(bb * VN + ww)) * 256 + kb2);
#pragma unroll
                        for (int i = 0; i < 4; i++) {
                            float4 fv = pv[i], fw = pw[i];
                            fa[4*i+0] = fabsf(fv.x - fw.x); fa[4*i+1] = fabsf(fv.y - fw.y);
                            fa[4*i+2] = fabsf(fv.z - fw.z); fa[4*i+3] = fabsf(fv.w - fw.w);
                        }
                    } else {
                        const float4* pa = (const float4*)(Ain + (size_t)gr * K + kb2);
#pragma unroll
                        for (int i = 0; i < 4; i++) {
                            float4 f = pa[i];
                            fa[4*i+0] = f.x; fa[4*i+1] = f.y; fa[4*i+2] = f.z; fa[4*i+3] = f.w;
                        }
                    }
                }
            }

            // ---- mma over chunk c (R13-verbatim fragment addressing and term order) ----
            const uint32_t bHb = sb + OFFB + c * 16384;
            const uint32_t bLb = bHb + NC * 16384;
#pragma unroll
            for (int ksi = 0; ksi < 4; ksi++) {
                uint32_t Ah[2][4], Al[2][4], Bh[2][4], Bl[2][4];
#pragma unroll
                for (int i = 0; i < 2; i++) {
                    uint32_t o = (uint32_t)(wm * 32 + i * 16 + (lane & 15)) * 128
                               + ksi * 32 + ((lane >> 4) << 4);
                    o ^= (o >> 3) & 0x70;
                    LDSM4(Ah[i], aH + o);
                    LDSM4(Al[i], aL + o);
                }
#pragma unroll
                for (int j16 = 0; j16 < 2; j16++) {
                    uint32_t o = (uint32_t)(wn * 32 + j16 * 16 + (lane & 7) + ((lane >> 4) << 3)) * 128
                               + ksi * 32 + (((lane >> 3) & 1) << 4);
                    o ^= (o >> 3) & 0x70;
                    LDSM4(Bh[j16], bHb + o);
                    LDSM4(Bl[j16], bLb + o);
                }
#pragma unroll
                for (int i = 0; i < 2; i++) {
#pragma unroll
                    for (int j = 0; j < 4; j++) {
                        uint32_t h0 = Bh[j >> 1][(j & 1) * 2], h1 = Bh[j >> 1][(j & 1) * 2 + 1];
                        uint32_t l0 = Bl[j >> 1][(j & 1) * 2], l1 = Bl[j >> 1][(j & 1) * 2 + 1];
                        MMA16816(facc[i][j], Ah[i], h0, h1);
                        MMA16816(facc[i][j], Ah[i], l0, l1);
                        MMA16816(facc[i][j], Al[i], h0, h1);
                    }
                }
            }
        }

        // ---------- epilogue (R13-verbatim) ----------
        float ps[8], pq8[8];
#pragma unroll
        for (int q = 0; q < 8; q++) { ps[q] = 0.f; pq8[q] = 0.f; }
        int mBase = mt * 128 + wm * 32;
#pragma unroll
        for (int i = 0; i < 2; i++) {
            int r0 = mBase + i * 16 + (lane >> 2);
            int r1 = r0 + 8;
            bool ok0 = r0 < MROWS, ok1 = r1 < MROWS;
            float wt0 = ok0 ? g_wpair[r0 % PAIRS] : 0.f;
            float wt1 = ok1 ? g_wpair[r1 % PAIRS] : 0.f;
#pragma unroll
            for (int j = 0; j < 4; j++) {
                int cc = wn * 32 + j * 8 + 2 * (lane & 3);
                float y0 = facc[i][j][0] + biasS[cc];
                float y1 = facc[i][j][1] + biasS[cc + 1];
                float y2 = facc[i][j][2] + biasS[cc];
                float y3 = facc[i][j][3] + biasS[cc + 1];
                if (ok0) *(float2*)&Cout[(size_t)r0 * ldc + colStart + cc] = make_float2(y0, y1);
                if (ok1) *(float2*)&Cout[(size_t)r1 * ldc + colStart + cc] = make_float2(y2, y3);
                ps[2*j]   += wt0 * y0 + wt1 * y2;
                ps[2*j+1] += wt0 * y1 + wt1 * y3;
                pq8[2*j]   += wt0 * y0 * y0 + wt1 * y2 * y2;
                pq8[2*j+1] += wt0 * y1 * y1 + wt1 * y3 * y3;
            }
        }
#pragma unroll
        for (int off = 4; off < 32; off <<= 1) {
#pragma unroll
            for (int q = 0; q < 8; q++) {
                ps[q]  += __shfl_xor_sync(0xffffffffu, ps[q], off);
                pq8[q] += __shfl_xor_sync(0xffffffffu, pq8[q], off);
            }
        }
        if (lane < 4) {
#pragma unroll
            for (int j = 0; j < 4; j++) {
                wSsum[w * 32 + j * 8 + 2 * lane]     = ps[2*j];
                wSsum[w * 32 + j * 8 + 2 * lane + 1] = ps[2*j+1];
                wSsq [w * 32 + j * 8 + 2 * lane]     = pq8[2*j];
                wSsq [w * 32 + j * 8 + 2 * lane + 1] = pq8[2*j+1];
            }
        }
        __syncthreads();
        if (tid < 128) {
            int base = (tid >> 5) * 128 + (tid & 31);
            sumAcc[tid] += wSsum[base] + wSsum[base + 32] + wSsum[base + 64] + wSsum[base + 96];
            sqAcc [tid] += wSsq [base] + wSsq [base + 32] + wSsq [base + 64] + wSsq [base + 96];
        }
        __syncthreads();
    }

    if (tid < 128) {
        g_psum[(size_t)(colStart + tid) * PSTRIDE + blockIdx.x] = sumAcc[tid];
        g_psq [(size_t)(colStart + tid) * PSTRIDE + blockIdx.x] = sqAcc[tid];
    }
}

// ---------------- reduce 148 partials -> BN affine ----------------
__global__ void stats2(int outOff, const float* __restrict__ gamma, const float* __restrict__ beta) {
    int c = blockIdx.x, t = threadIdx.x;
    double s = 0.0, q = 0.0;
    for (int i = t; i < NCTA; i += 32) {
        s += (double)g_psum[(size_t)c * PSTRIDE + i];
        q += (double)g_psq [(size_t)c * PSTRIDE + i];
    }
#pragma unroll
    for (int o = 16; o > 0; o >>= 1) {
        s += __shfl_down_sync(0xffffffffu, s, o);
        q += __shfl_down_sync(0xffffffffu, q, o);
    }
    if (t == 0) {
        double mean = s / CNT;
        double var  = q / CNT - mean * mean;
        float inv = rsqrtf((float)var + 1e-5f);
        float sc  = gamma[c] * inv;
        g_sArr[outOff + c] = sc;
        g_tArr[outOff + c] = beta[c] - (float)mean * sc;
    }
}

// ---------------- final linear -> symmetric logit scatter ----------------
__global__ void logits_kernel(const float* __restrict__ w4, const float* __restrict__ b4) {
    int warp = threadIdx.x >> 5, lane = threadIdx.x & 31;
    int r = blockIdx.x * 8 + warp;
    if (r >= MROWS) return;
    int c = lane * 4;
    float4 v  = *(const float4*)&g_bufA[(size_t)r * 128 + c];
    float4 s4 = *(const float4*)&g_sArr[768 + c];
    float4 t4 = *(const float4*)&g_tArr[768 + c];
    float4 w  = *(const float4*)&w4[c];
    float a, sum = 0.f;
    a = v.x * s4.x + t4.x; a = a >= 0.f ? a : LSLOPE * a; sum += a * w.x;
    a = v.y * s4.y + t4.y; a = a >= 0.f ? a : LSLOPE * a; sum += a * w.y;
    a = v.z * s4.z + t4.z; a = a >= 0.f ? a : LSLOPE * a; sum += a * w.z;
    a = v.w * s4.w + t4.w; a = a >= 0.f ? a : LSLOPE * a; sum += a * w.w;
#pragma unroll
    for (int off = 16; off > 0; off >>= 1) sum += __shfl_down_sync(0xffffffffu, sum, off);
    if (lane == 0) {
        float lg = sum + b4[0];
        int b = r / PAIRS, p = r - b * PAIRS;
        int2 vw = g_vw[p];
        g_logits[((size_t)b * VN + vw.x) * VN + vw.y] = lg;
        g_logits[((size_t)b * VN + vw.y) * VN + vw.x] = lg;
    }
}

// ---------------- row softmax + top-K mask ----------------
__global__ void softmax_topk(float* __restrict__ out) {
    int bv = blockIdx.x;
    int b = bv / VN, v = bv % VN;
    int t = threadIdx.x;
    __shared__ float sl[204];
    __shared__ float red[256];

    float lv = -3.402823466e38f;
    if (t < VN) { lv = g_logits[((size_t)b * VN + v) * VN + t]; sl[t] = lv; }
    red[t] = lv;
    __syncthreads();
    for (int s = 128; s > 0; s >>= 1) {
        if (t < s) red[t] = fmaxf(red[t], red[t + s]);
        __syncthreads();
    }
    float mx = red[0];
    __syncthreads();
    float e = (t < VN) ? __expf(lv - mx) : 0.f;
    red[t] = e;
    __syncthreads();
    for (int s = 128; s > 0; s >>= 1) {
        if (t < s) red[t] += red[t + s];
        __syncthreads();
    }
    float inv = 1.f / red[0];
    if (t < VN) {
        int cnt = 0;
        for (int j = 0; j < VN; j++) {
            float lj = sl[j];
            cnt += (lj > lv) || (lj == lv && j < t);
        }
        out[((size_t)b * VN + v) * VN + t] = (cnt < KSEL) ? e * inv : 0.f;
    }
}

// ---------------- launch ----------------
extern "C" void kernel_launch(void* const* d_in, const int* in_sizes, int n_in,
                              void* d_out, int out_size)
{
    (void)in_sizes; (void)n_in; (void)out_size;
    const float* x   = (const float*)d_in[0];
    const float* w0  = (const float*)d_in[1];
    const float* b0  = (const float*)d_in[2];
    const float* g0  = (const float*)d_in[3];
    const float* be0 = (const float*)d_in[4];
    const float* w1  = (const float*)d_in[5];
    const float* b1  = (const float*)d_in[6];
    const float* g1  = (const float*)d_in[7];
    const float* be1 = (const float*)d_in[8];
    const float* w2  = (const float*)d_in[9];
    const float* b2  = (const float*)d_in[10];
    const float* g2  = (const float*)d_in[11];
    const float* be2 = (const float*)d_in[12];
    const float* w3  = (const float*)d_in[13];
    const float* b3  = (const float*)d_in[14];
    const float* g3  = (const float*)d_in[15];
    const float* be3 = (const float*)d_in[16];
    const float* w4  = (const float*)d_in[17];
    const float* b4  = (const float*)d_in[18];

    const int SM256 = OFFB + 8 * 16384;   // 204800
    const int SM128 = OFFB + 4 * 16384;   // 139264
    cudaFuncSetAttribute(gemm_mma<256, 0, 0>, cudaFuncAttributeMaxDynamicSharedMemorySize, SM256);
    cudaFuncSetAttribute(gemm_mma<256, 1, 1>, cudaFuncAttributeMaxDynamicSharedMemorySize, SM256);
    cudaFuncSetAttribute(gemm_mma<256, 1, 0>, cudaFuncAttributeMaxDynamicSharedMemorySize, SM256);
    cudaFuncSetAttribute(gemm_mma<128, 1, 1>, cudaFuncAttributeMaxDynamicSharedMemorySize, SM128);

    init_all<<<64, 256>>>(w0, w1, w2, w3);

    // L0: absdiff(x) @ w0^T -> bufB   (K=256, N=256)
    gemm_mma<256, 0, 0><<<dim3(NCTA, 2), 512, SM256>>>(256, 0, x, b0, 0);
    stats2<<<256, 32>>>(0, g0, be0);

    // L1: act(bn0(bufB)) @ w1^T -> bufA   (K=256, N=256)
    gemm_mma<256, 1, 1><<<dim3(NCTA, 2), 512, SM256>>>(256, 65536, x, b1, 0);
    stats2<<<256, 32>>>(256, g1, be1);

    // L2: act(bn1(bufA)) @ w2^T -> bufB   (K=256, N=128)
    gemm_mma<256, 1, 0><<<dim3(NCTA, 1), 512, SM256>>>(128, 131072, x, b2, 256);
    stats2<<<128, 32>>>(512, g2, be2);

    // L3: act(bn2(bufB)) @ w3^T -> bufA   (K=128, N=128)
    gemm_mma<128, 1, 1><<<dim3(NCTA, 1), 512, SM128>>>(128, 163840, x, b3, 512);
    stats2<<<128, 32>>>(768, g3, be3);

    // L4 + symmetric scatter, then softmax/top-K
    logits_kernel<<<MROWS / 8, 256>>>(w4, b4);
    softmax_topk<<<BATCH * VN, 256>>>((float*)d_out);
}

// round 15
// speedup vs baseline: 1.0949x; 1.0949x over previous
#include <cuda_runtime.h>
#include <cuda_bf16.h>
#include <cstdint>

#define BATCH   8
#define VN      201
#define PAIRS   20301
#define MROWS   162408
#define TILESM  1269
#define KSEL    100
#define LSLOPE  0.01f
#define CNT     323208.0
#define PSTRIDE 160

// smem: header 8KB | A 32KB (hi16+lo16) | B NC*16KB hi + NC*16KB lo
#define OFFA 8192
#define OFFB (OFFA + 32768)

// ---------------- device scratch ----------------
__device__ float g_bufA[MROWS * 256];
__device__ float g_bufB[MROWS * 256];
__device__ int2  g_vw[PAIRS];
__device__ float g_wpair[PAIRS];
__device__ float g_psum[256 * PSTRIDE];
__device__ float g_psq [256 * PSTRIDE];
__device__ float g_sArr[1024];
__device__ float g_tArr[1024];
__device__ float g_logits[BATCH * VN * VN];
__device__ __nv_bfloat16 g_whi[180224];
__device__ __nv_bfloat16 g_wlo[180224];

// ---------------- PTX helpers ----------------
__device__ __forceinline__ uint32_t smem_u32(const void* p) {
    uint32_t a;
    asm("{ .reg .u64 t; cvta.to.shared.u64 t, %1; cvt.u32.u64 %0, t; }" : "=r"(a) : "l"(p));
    return a;
}
#define STS128(r0, r1, r2, r3, a) \
    asm volatile("st.shared.v4.b32 [%0], {%1, %2, %3, %4};" \
                 :: "r"(a), "r"(r0), "r"(r1), "r"(r2), "r"(r3) : "memory")
#define LDSM4(R, a) \
    asm volatile("ldmatrix.sync.aligned.m8n8.x4.shared.b16 {%0,%1,%2,%3}, [%4];" \
                 : "=r"((R)[0]), "=r"((R)[1]), "=r"((R)[2]), "=r"((R)[3]) : "r"(a))
#define MMA16816(c, A, b0, b1) \
    asm volatile("mma.sync.aligned.m16n8k16.row.col.f32.bf16.bf16.f32 " \
                 "{%0,%1,%2,%3}, {%4,%5,%6,%7}, {%8,%9}, {%0,%1,%2,%3};" \
                 : "+f"((c)[0]), "+f"((c)[1]), "+f"((c)[2]), "+f"((c)[3]) \
                 : "r"((A)[0]), "r"((A)[1]), "r"((A)[2]), "r"((A)[3]), "r"(b0), "r"(b1))

// ---------------- init: pair LUT + weight split (fused) ----------------
__global__ void init_all(const float* __restrict__ w0, const float* __restrict__ w1,
                         const float* __restrict__ w2, const float* __restrict__ w3) {
    int t = blockIdx.x * blockDim.x + threadIdx.x;
    int st = gridDim.x * blockDim.x;
    if (blockIdx.x == 0) {
        for (int v = threadIdx.x; v < VN; v += blockDim.x) {
            int base = v * VN - (v * (v - 1)) / 2;
            for (int w = v; w < VN; w++) {
                int p = base + (w - v);
                g_vw[p] = make_int2(v, w);
                g_wpair[p] = (v == w) ? 1.0f : 2.0f;
            }
        }
    }
    for (int i = t; i < 65536; i += st) {
        float v = w0[i]; __nv_bfloat16 h = __float2bfloat16(v);
        g_whi[i] = h; g_wlo[i] = __float2bfloat16(v - __bfloat162float(h));
    }
    for (int i = t; i < 65536; i += st) {
        float v = w1[i]; __nv_bfloat16 h = __float2bfloat16(v);
        g_whi[65536 + i] = h; g_wlo[65536 + i] = __float2bfloat16(v - __bfloat162float(h));
    }
    for (int i = t; i < 32768; i += st) {
        float v = w2[i]; __nv_bfloat16 h = __float2bfloat16(v);
        g_whi[131072 + i] = h; g_wlo[131072 + i] = __float2bfloat16(v - __bfloat162float(h));
    }
    for (int i = t; i < 16384; i += st) {
        float v = w3[i]; __nv_bfloat16 h = __float2bfloat16(v);
        g_whi[163840 + i] = h; g_wlo[163840 + i] = __float2bfloat16(v - __bfloat162float(h));
    }
}

// ---------------- persistent mma.sync bf16-split GEMM: 512 threads, resident B (R13) ----------------
// MODE 0: A = |x_v - x_w| on the fly.  MODE 1: A = LeakyReLU(affine(prev)).
// SRC 0: Ain=g_bufA, C=g_bufB.  SRC 1: Ain=g_bufB, C=g_bufA.
template<int K, int MODE, int SRC>
__global__ __launch_bounds__(512, 1)
void gemm_mma(int ldc, int wOff, const float* __restrict__ x,
              const float* __restrict__ bias, int affOff)
{
    constexpr int NC = K / 64;
    const float* Ain  = (SRC == 0) ? g_bufA : g_bufB;
    float*       Cout = (SRC == 0) ? g_bufB : g_bufA;

    extern __shared__ char sm[];
    uint32_t sb = smem_u32(sm);
    const int tid  = threadIdx.x;
    const int lane = tid & 31;
    const int w    = tid >> 5;          // 0..15
    const int wm   = w & 3;             // 4 m-slabs of 32 rows
    const int wn   = w >> 2;            // 4 n-slabs of 32 cols
    const int colStart = blockIdx.y * 128;
    const int mtStride = gridDim.x;

    float* biasS  = (float*)(sm + 0);
    float* sumAcc = (float*)(sm + 512);
    float* sqAcc  = (float*)(sm + 1024);
    float* sS     = (float*)(sm + 1536);
    float* tS     = (float*)(sm + 2560);
    float* wSsum  = (float*)(sm + 3584);   // 16 warps x 32
    float* wSsq   = (float*)(sm + 5632);   // 16 warps x 32

    if (tid < 128) { biasS[tid] = bias[colStart + tid]; sumAcc[tid] = 0.f; sqAcc[tid] = 0.f; }
    if (MODE == 1) {
        for (int i = tid; i < K; i += 512) { sS[i] = g_sArr[affOff + i]; tS[i] = g_tArr[affOff + i]; }
    }

    // ---- B (weight hi/lo) resident in smem, SW128 swizzled [n][64k] rows ----
    for (int i = tid; i < NC * 128; i += 512) {
        int c = i >> 7, n = i & 127;
        const uint4* srcH = (const uint4*)(g_whi + (size_t)wOff + (size_t)(colStart + n) * K + c * 64);
        const uint4* srcL = (const uint4*)(g_wlo + (size_t)wOff + (size_t)(colStart + n) * K + c * 64);
        uint32_t baseH = sb + OFFB + c * 16384;
        uint32_t baseL = sb + OFFB + NC * 16384 + c * 16384;
#pragma unroll
        for (int u = 0; u < 8; u++) {
            uint4 vH = srcH[u]; uint4 vL = srcL[u];
            uint32_t o = n * 128 + u * 16; o ^= (o >> 3) & 0x70;
            STS128(vH.x, vH.y, vH.z, vH.w, baseH + o);
            STS128(vL.x, vL.y, vL.z, vL.w, baseL + o);
        }
    }
    __syncthreads();   // B ready

    const int prow = tid >> 2;          // 0..127 (A row)
    const int pq   = tid & 3;           // 16-elem column quarter

    for (int mt = blockIdx.x; mt < TILESM; mt += mtStride) {
        int gr = mt * 128 + prow;
        bool ok = gr < MROWS;
        int vv = 0, ww = 0, bb = 0;
        if (MODE == 0 && ok) {
            bb = gr / PAIRS; int p = gr - bb * PAIRS;
            int2 vw2 = g_vw[p]; vv = vw2.x; ww = vw2.y;
        }

        float facc[2][4][4];
#pragma unroll
        for (int i = 0; i < 2; i++)
#pragma unroll
            for (int j = 0; j < 4; j++)
#pragma unroll
                for (int q = 0; q < 4; q++) facc[i][j][q] = 0.f;

        float fa[16];
        // load chunk 0
        {
            int kb = pq * 16;
            if (ok) {
                if (MODE == 0) {
                    const float4* pv = (const float4*)(x + ((size_t)(bb * VN + vv)) * 256 + kb);
                    const float4* pw = (const float4*)(x + ((size_t)(bb * VN + ww)) * 256 + kb);
#pragma unroll
                    for (int i = 0; i < 4; i++) {
                        float4 fv = pv[i], fw = pw[i];
                        fa[4*i+0] = fabsf(fv.x - fw.x); fa[4*i+1] = fabsf(fv.y - fw.y);
                        fa[4*i+2] = fabsf(fv.z - fw.z); fa[4*i+3] = fabsf(fv.w - fw.w);
                    }
                } else {
                    const float4* pa = (const float4*)(Ain + (size_t)gr * K + kb);
#pragma unroll
                    for (int i = 0; i < 4; i++) {
                        float4 f = pa[i];
                        fa[4*i+0] = f.x; fa[4*i+1] = f.y; fa[4*i+2] = f.z; fa[4*i+3] = f.w;
                    }
                }
            } else {
#pragma unroll
                for (int i = 0; i < 16; i++) fa[i] = 0.f;
            }
        }

        for (int c = 0; c < NC; c++) {
            int kb = c * 64 + pq * 16;
            // convert fa -> hi/lo bf16x2 (affine+act for MODE 1)
            uint32_t hp[8], lp[8];
#pragma unroll
            for (int i = 0; i < 8; i++) {
                float f0 = fa[2*i], f1 = fa[2*i+1];
                if (MODE == 1) {
                    f0 = fmaf(f0, sS[kb + 2*i],     tS[kb + 2*i]);
                    f1 = fmaf(f1, sS[kb + 2*i + 1], tS[kb + 2*i + 1]);
                    f0 = f0 >= 0.f ? f0 : LSLOPE * f0;
                    f1 = f1 >= 0.f ? f1 : LSLOPE * f1;
                }
                uint32_t h;
                asm("cvt.rn.bf16x2.f32 %0, %1, %2;" : "=r"(h) : "f"(f1), "f"(f0));
                __nv_bfloat162 hh = *reinterpret_cast<__nv_bfloat162*>(&h);
                float r0 = f0 - __bfloat162float(hh.x);
                float r1 = f1 - __bfloat162float(hh.y);
                uint32_t l;
                asm("cvt.rn.bf16x2.f32 %0, %1, %2;" : "=r"(l) : "f"(r1), "f"(r0));
                hp[i] = h; lp[i] = l;
            }

            __syncthreads();   // previous mma phase done with A buffer

            const uint32_t aH = sb + OFFA;
            const uint32_t aL = aH + 16384;
#pragma unroll
            for (int u = 0; u < 2; u++) {
                uint32_t o = prow * 128 + pq * 32 + u * 16; o ^= (o >> 3) & 0x70;
                STS128(hp[4*u], hp[4*u+1], hp[4*u+2], hp[4*u+3], aH + o);
                STS128(lp[4*u], lp[4*u+1], lp[4*u+2], lp[4*u+3], aL + o);
            }
            __syncthreads();   // A chunk visible

            // prefetch next chunk's globals into registers (hidden under mma)
            if (c + 1 < NC) {
                const int kb2 = (c + 1) * 64 + pq * 16;
                if (ok) {
                    if (MODE == 0) {
                        const float4* pv = (const float4*)(x + ((size_t)(bb * VN + vv)) * 256 + kb2);
                        const float4* pw = (const float4*)(x + ((size_t)(bb * VN + ww)) * 256 + kb2);
#pragma unroll
                        for (int i = 0; i < 4; i++) {
                            float4 fv = pv[i], fw = pw[i];
                            fa[4*i+0] = fabsf(fv.x - fw.x); fa[4*i+1] = fabsf(fv.y - fw.y);
                            fa[4*i+2] = fabsf(fv.z - fw.z); fa[4*i+3] = fabsf(fv.w - fw.w);
                        }
                    } else {
                        const float4* pa = (const float4*)(Ain + (size_t)gr * K + kb2);
#pragma unroll
                        for (int i = 0; i < 4; i++) {
                            float4 f = pa[i];
                            fa[4*i+0] = f.x; fa[4*i+1] = f.y; fa[4*i+2] = f.z; fa[4*i+3] = f.w;
                        }
                    }
                }
            }

            // ---- mma over chunk c (R13-verbatim fragment addressing and term order) ----
            const uint32_t bHb = sb + OFFB + c * 16384;
            const uint32_t bLb = bHb + NC * 16384;
#pragma unroll
            for (int ksi = 0; ksi < 4; ksi++) {
                uint32_t Ah[2][4], Al[2][4], Bh[2][4], Bl[2][4];
#pragma unroll
                for (int i = 0; i < 2; i++) {
                    uint32_t o = (uint32_t)(wm * 32 + i * 16 + (lane & 15)) * 128
                               + ksi * 32 + ((lane >> 4) << 4);
                    o ^= (o >> 3) & 0x70;
                    LDSM4(Ah[i], aH + o);
                    LDSM4(Al[i], aL + o);
                }
#pragma unroll
                for (int j16 = 0; j16 < 2; j16++) {
                    uint32_t o = (uint32_t)(wn * 32 + j16 * 16 + (lane & 7) + ((lane >> 4) << 3)) * 128
                               + ksi * 32 + (((lane >> 3) & 1) << 4);
                    o ^= (o >> 3) & 0x70;
                    LDSM4(Bh[j16], bHb + o);
                    LDSM4(Bl[j16], bLb + o);
                }
#pragma unroll
                for (int i = 0; i < 2; i++) {
#pragma unroll
                    for (int j = 0; j < 4; j++) {
                        uint32_t h0 = Bh[j >> 1][(j & 1) * 2], h1 = Bh[j >> 1][(j & 1) * 2 + 1];
                        uint32_t l0 = Bl[j >> 1][(j & 1) * 2], l1 = Bl[j >> 1][(j & 1) * 2 + 1];
                        MMA16816(facc[i][j], Ah[i], h0, h1);
                        MMA16816(facc[i][j], Ah[i], l0, l1);
                        MMA16816(facc[i][j], Al[i], h0, h1);
                    }
                }
            }
        }

        // ---------- epilogue (R13-verbatim) ----------
        float ps[8], pq8[8];
#pragma unroll
        for (int q = 0; q < 8; q++) { ps[q] = 0.f; pq8[q] = 0.f; }
        int mBase = mt * 128 + wm * 32;
#pragma unroll
        for (int i = 0; i < 2; i++) {
            int r0 = mBase + i * 16 + (lane >> 2);
            int r1 = r0 + 8;
            bool ok0 = r0 < MROWS, ok1 = r1 < MROWS;
            float wt0 = ok0 ? g_wpair[r0 % PAIRS] : 0.f;
            float wt1 = ok1 ? g_wpair[r1 % PAIRS] : 0.f;
#pragma unroll
            for (int j = 0; j < 4; j++) {
                int cc = wn * 32 + j * 8 + 2 * (lane & 3);
                float y0 = facc[i][j][0] + biasS[cc];
                float y1 = facc[i][j][1] + biasS[cc + 1];
                float y2 = facc[i][j][2] + biasS[cc];
                float y3 = facc[i][j][3] + biasS[cc + 1];
                if (ok0) *(float2*)&Cout[(size_t)r0 * ldc + colStart + cc] = make_float2(y0, y1);
                if (ok1) *(float2*)&Cout[(size_t)r1 * ldc + colStart + cc] = make_float2(y2, y3);
                ps[2*j]   += wt0 * y0 + wt1 * y2;
                ps[2*j+1] += wt0 * y1 + wt1 * y3;
                pq8[2*j]   += wt0 * y0 * y0 + wt1 * y2 * y2;
                pq8[2*j+1] += wt0 * y1 * y1 + wt1 * y3 * y3;
            }
        }
#pragma unroll
        for (int off = 4; off < 32; off <<= 1) {
#pragma unroll
            for (int q = 0; q < 8; q++) {
                ps[q]  += __shfl_xor_sync(0xffffffffu, ps[q], off);
                pq8[q] += __shfl_xor_sync(0xffffffffu, pq8[q], off);
            }
        }
        if (lane < 4) {
#pragma unroll
            for (int j = 0; j < 4; j++) {
                wSsum[w * 32 + j * 8 + 2 * lane]     = ps[2*j];
                wSsum[w * 32 + j * 8 + 2 * lane + 1] = ps[2*j+1];
                wSsq [w * 32 + j * 8 + 2 * lane]     = pq8[2*j];
                wSsq [w * 32 + j * 8 + 2 * lane + 1] = pq8[2*j+1];
            }
        }
        __syncthreads();
        if (tid < 128) {
            int base = (tid >> 5) * 128 + (tid & 31);
            sumAcc[tid] += wSsum[base] + wSsum[base + 32] + wSsum[base + 64] + wSsum[base + 96];
            sqAcc [tid] += wSsq [base] + wSsq [base + 32] + wSsq [base + 64] + wSsq [base + 96];
        }
        __syncthreads();
    }

    if (tid < 128) {
        g_psum[(size_t)(colStart + tid) * PSTRIDE + blockIdx.x] = sumAcc[tid];
        g_psq [(size_t)(colStart + tid) * PSTRIDE + blockIdx.x] = sqAcc[tid];
    }
}

// ---------------- reduce nPart partials -> BN affine ----------------
__global__ void stats2(int outOff, int nPart,
                       const float* __restrict__ gamma, const float* __restrict__ beta) {
    int c = blockIdx.x, t = threadIdx.x;
    double s = 0.0, q = 0.0;
    for (int i = t; i < nPart; i += 32) {
        s += (double)g_psum[(size_t)c * PSTRIDE + i];
        q += (double)g_psq [(size_t)c * PSTRIDE + i];
    }
#pragma unroll
    for (int o = 16; o > 0; o >>= 1) {
        s += __shfl_down_sync(0xffffffffu, s, o);
        q += __shfl_down_sync(0xffffffffu, q, o);
    }
    if (t == 0) {
        double mean = s / CNT;
        double var  = q / CNT - mean * mean;
        float inv = rsqrtf((float)var + 1e-5f);
        float sc  = gamma[c] * inv;
        g_sArr[outOff + c] = sc;
        g_tArr[outOff + c] = beta[c] - (float)mean * sc;
    }
}

// ---------------- final linear -> symmetric logit scatter ----------------
__global__ void logits_kernel(const float* __restrict__ w4, const float* __restrict__ b4) {
    int warp = threadIdx.x >> 5, lane = threadIdx.x & 31;
    int r = blockIdx.x * 8 + warp;
    if (r >= MROWS) return;
    int c = lane * 4;
    float4 v  = *(const float4*)&g_bufA[(size_t)r * 128 + c];
    float4 s4 = *(const float4*)&g_sArr[768 + c];
    float4 t4 = *(const float4*)&g_tArr[768 + c];
    float4 w  = *(const float4*)&w4[c];
    float a, sum = 0.f;
    a = v.x * s4.x + t4.x; a = a >= 0.f ? a : LSLOPE * a; sum += a * w.x;
    a = v.y * s4.y + t4.y; a = a >= 0.f ? a : LSLOPE * a; sum += a * w.y;
    a = v.z * s4.z + t4.z; a = a >= 0.f ? a : LSLOPE * a; sum += a * w.z;
    a = v.w * s4.w + t4.w; a = a >= 0.f ? a : LSLOPE * a; sum += a * w.w;
#pragma unroll
    for (int off = 16; off > 0; off >>= 1) sum += __shfl_down_sync(0xffffffffu, sum, off);
    if (lane == 0) {
        float lg = sum + b4[0];
        int b = r / PAIRS, p = r - b * PAIRS;
        int2 vw = g_vw[p];
        g_logits[((size_t)b * VN + vw.x) * VN + vw.y] = lg;
        g_logits[((size_t)b * VN + vw.y) * VN + vw.x] = lg;
    }
}

// ---------------- row softmax + top-K mask ----------------
__global__ void softmax_topk(float* __restrict__ out) {
    int bv = blockIdx.x;
    int b = bv / VN, v = bv % VN;
    int t = threadIdx.x;
    __shared__ float sl[204];
    __shared__ float red[256];

    float lv = -3.402823466e38f;
    if (t < VN) { lv = g_logits[((size_t)b * VN + v) * VN + t]; sl[t] = lv; }
    red[t] = lv;
    __syncthreads();
    for (int s = 128; s > 0; s >>= 1) {
        if (t < s) red[t] = fmaxf(red[t], red[t + s]);
        __syncthreads();
    }
    float mx = red[0];
    __syncthreads();
    float e = (t < VN) ? __expf(lv - mx) : 0.f;
    red[t] = e;
    __syncthreads();
    for (int s = 128; s > 0; s >>= 1) {
        if (t < s) red[t] += red[t + s];
        __syncthreads();
    }
    float inv = 1.f / red[0];
    if (t < VN) {
        int cnt = 0;
        for (int j = 0; j < VN; j++) {
            float lj = sl[j];
            cnt += (lj > lv) || (lj == lv && j < t);
        }
        out[((size_t)b * VN + v) * VN + t] = (cnt < KSEL) ? e * inv : 0.f;
    }
}

// ---------------- launch ----------------
extern "C" void kernel_launch(void* const* d_in, const int* in_sizes, int n_in,
                              void* d_out, int out_size)
{
    (void)in_sizes; (void)n_in; (void)out_size;
    const float* x   = (const float*)d_in[0];
    const float* w0  = (const float*)d_in[1];
    const float* b0  = (const float*)d_in[2];
    const float* g0  = (const float*)d_in[3];
    const float* be0 = (const float*)d_in[4];
    const float* w1  = (const float*)d_in[5];
    const float* b1  = (const float*)d_in[6];
    const float* g1  = (const float*)d_in[7];
    const float* be1 = (const float*)d_in[8];
    const float* w2  = (const float*)d_in[9];
    const float* b2  = (const float*)d_in[10];
    const float* g2  = (const float*)d_in[11];
    const float* be2 = (const float*)d_in[12];
    const float* w3  = (const float*)d_in[13];
    const float* b3  = (const float*)d_in[14];
    const float* g3  = (const float*)d_in[15];
    const float* be3 = (const float*)d_in[16];
    const float* w4  = (const float*)d_in[17];
    const float* b4  = (const float*)d_in[18];

    const int SM256 = OFFB + 8 * 16384;   // 172032
    const int SM128 = OFFB + 4 * 16384;   // 106496
    cudaFuncSetAttribute(gemm_mma<256, 0, 0>, cudaFuncAttributeMaxDynamicSharedMemorySize, SM256);
    cudaFuncSetAttribute(gemm_mma<256, 1, 1>, cudaFuncAttributeMaxDynamicSharedMemorySize, SM256);
    cudaFuncSetAttribute(gemm_mma<256, 1, 0>, cudaFuncAttributeMaxDynamicSharedMemorySize, SM256);
    cudaFuncSetAttribute(gemm_mma<128, 1, 1>, cudaFuncAttributeMaxDynamicSharedMemorySize, SM128);

    init_all<<<64, 256>>>(w0, w1, w2, w3);

    // L0: absdiff(x) @ w0^T -> bufB   (K=256, N=256): 74x2 = 148 CTAs, one wave
    gemm_mma<256, 0, 0><<<dim3(74, 2), 512, SM256>>>(256, 0, x, b0, 0);
    stats2<<<256, 32>>>(0, 74, g0, be0);

    // L1: act(bn0(bufB)) @ w1^T -> bufA   (K=256, N=256)
    gemm_mma<256, 1, 1><<<dim3(74, 2), 512, SM256>>>(256, 65536, x, b1, 0);
    stats2<<<256, 32>>>(256, 74, g1, be1);

    // L2: act(bn1(bufA)) @ w2^T -> bufB   (K=256, N=128): 148 CTAs, one wave
    gemm_mma<256, 1, 0><<<dim3(148, 1), 512, SM256>>>(128, 131072, x, b2, 256);
    stats2<<<128, 32>>>(512, 148, g2, be2);

    // L3: act(bn2(bufB)) @ w3^T -> bufA   (K=128, N=128)
    gemm_mma<128, 1, 1><<<dim3(148, 1), 512, SM128>>>(128, 163840, x, b3, 512);
    stats2<<<128, 32>>>(768, 148, g3, be3);

    // L4 + symmetric scatter, then softmax/top-K
    logits_kernel<<<MROWS / 8, 256>>>(w4, b4);
    softmax_topk<<<BATCH * VN, 256>>>((float*)d_out);
}